// round 12
// baseline (speedup 1.0000x reference)
#include <cuda_runtime.h>
#include <cuda_fp16.h>
#include <cstdint>

// Problem dims (fixed by dataset)
#define BB 8
#define NN 2048
#define CC 128
#define NQT 16  // NN / 128

// ---------------- scratch (device globals; no allocs allowed) ----------------
__device__ unsigned short g_hn[BB * NN * CC];  // normalized h, fp16, [b][n][c]
__device__ float g_norm[BB * NN];              // per-row L2 norm of h (fp32)

// ---------------- PTX helpers (family-portable: sm_75/80-era) ----------------
__device__ __forceinline__ uint32_t smem_u32(const void* p) {
    uint32_t a;
    asm("{ .reg .u64 t; cvta.to.shared.u64 t, %1; cvt.u32.u64 %0, t; }" : "=r"(a) : "l"(p));
    return a;
}

__device__ __forceinline__ void cp_async16(uint32_t dst, const void* src) {
    asm volatile("cp.async.cg.shared.global [%0], [%1], 16;" :: "r"(dst), "l"(src) : "memory");
}
#define CP_COMMIT() asm volatile("cp.async.commit_group;" ::: "memory")
#define CP_WAIT0()  asm volatile("cp.async.wait_group 0;" ::: "memory")

__device__ __forceinline__ void ldsm_x4(uint32_t* r, uint32_t a) {
    asm volatile("ldmatrix.sync.aligned.m8n8.x4.shared.b16 {%0,%1,%2,%3}, [%4];"
                 : "=r"(r[0]), "=r"(r[1]), "=r"(r[2]), "=r"(r[3]) : "r"(a));
}

// in-register 8x8 b16 transpose: converts MMA1 B-fragments into MMA2 B-fragments
__device__ __forceinline__ uint32_t movm(uint32_t a) {
    uint32_t d;
    asm volatile("movmatrix.sync.aligned.m8n8.trans.b16 %0, %1;" : "=r"(d) : "r"(a));
    return d;
}

__device__ __forceinline__ void mma16816(float* d, const uint32_t* a, uint32_t b0, uint32_t b1) {
    asm volatile("mma.sync.aligned.m16n8k16.row.col.f32.f16.f16.f32 "
                 "{%0,%1,%2,%3}, {%4,%5,%6,%7}, {%8,%9}, {%0,%1,%2,%3};"
                 : "+f"(d[0]), "+f"(d[1]), "+f"(d[2]), "+f"(d[3])
                 : "r"(a[0]), "r"(a[1]), "r"(a[2]), "r"(a[3]), "r"(b0), "r"(b1));
}

// pack two f32 -> f16x2 (lo = first arg)
__device__ __forceinline__ uint32_t pack_h2(float lo, float hi) {
    uint32_t d;
    asm("cvt.rn.f16x2.f32 %0, %1, %2;" : "=r"(d) : "f"(hi), "f"(lo));
    return d;
}

__device__ __forceinline__ float2 ldg2(const float* p) {
    float2 v;
    asm volatile("ld.global.nc.v2.f32 {%0,%1}, [%2];" : "=f"(v.x), "=f"(v.y) : "l"(p));
    return v;
}

// =====================================================================
// Kernel 1: h = x@W^T + b (fp16 MMA) ; norm = ||h|| ; g_hn = h/norm (fp16)
// grid (16,8), 256 threads (8 warps x m16). SMEM: x-tile + W-tile fp16.
// =====================================================================
#define TILE_B 34816                     // 128 rows * 272B (fp16 tile, padded)
#define K1_SMEM (2 * TILE_B + 512)

__global__ __launch_bounds__(256) void k1_linear_norm(const float* __restrict__ x,
                                                      const float* __restrict__ W,
                                                      const float* __restrict__ bias) {
    extern __shared__ char sm1[];
    char* xs = sm1;                 // x tile fp16 (reused as hn stage later)
    char* Ws = sm1 + TILE_B;        // W tile fp16
    float* bs = (float*)(sm1 + 2 * TILE_B);

    const int b = blockIdx.y;
    const int nb0 = blockIdx.x * 128;
    const int tid = threadIdx.x, wid = tid >> 5, lane = tid & 31;

    // stage x and W (fp32 -> fp16), pitch 272B
    {
        const float* xg = x + ((size_t)b * NN + nb0) * CC;
#pragma unroll
        for (int it = 0; it < 16; it++) {
            int i = tid + it * 256;
            int row = i >> 5, c4 = i & 31;
            float4 v = *(const float4*)(xg + (size_t)row * 128 + c4 * 4);
            *(uint2*)(xs + row * 272 + c4 * 8) = make_uint2(pack_h2(v.x, v.y), pack_h2(v.z, v.w));
            float4 w4 = *(const float4*)(W + (size_t)row * 128 + c4 * 4);
            *(uint2*)(Ws + row * 272 + c4 * 8) = make_uint2(pack_h2(w4.x, w4.y), pack_h2(w4.z, w4.w));
        }
        if (tid < 32) *(float4*)&bs[tid * 4] = *(const float4*)(bias + tid * 4);
    }
    __syncthreads();

    // A fragments: warp's m16 rows of x
    uint32_t af[32];
    {
        uint32_t xa = smem_u32(xs) + (uint32_t)((wid * 16 + (lane & 15)) * 272)
                    + ((lane & 16) ? 16 : 0);
#pragma unroll
        for (int kk = 0; kk < 8; kk++) ldsm_x4(af + 4 * kk, xa + kk * 32);
    }

    float Hf[64];
#pragma unroll
    for (int i = 0; i < 64; i++) Hf[i] = 0.0f;

    // B = W rows (o = n dim), non-trans x4 (n16 x k16 per load)
    {
        uint32_t wb = smem_u32(Ws) + (uint32_t)(((lane & 7) + ((lane & 16) ? 8 : 0)) * 272)
                    + ((lane & 8) ? 16 : 0);
#pragma unroll
        for (int jp = 0; jp < 8; jp++) {
#pragma unroll
            for (int kk = 0; kk < 8; kk++) {
                uint32_t bf[4];
                ldsm_x4(bf, wb + (uint32_t)(jp * 16 * 272) + kk * 32);
                mma16816(Hf + (jp * 2) * 4, af + 4 * kk, bf[0], bf[1]);
                mma16816(Hf + (jp * 2 + 1) * 4, af + 4 * kk, bf[2], bf[3]);
            }
        }
    }

    // bias + row sum-of-squares
    float s0 = 0.0f, s1 = 0.0f;
#pragma unroll
    for (int j = 0; j < 16; j++) {
        float2 bv = *(const float2*)&bs[j * 8 + 2 * (lane & 3)];
        Hf[j * 4 + 0] += bv.x; Hf[j * 4 + 1] += bv.y;
        Hf[j * 4 + 2] += bv.x; Hf[j * 4 + 3] += bv.y;
        s0 += Hf[j * 4 + 0] * Hf[j * 4 + 0] + Hf[j * 4 + 1] * Hf[j * 4 + 1];
        s1 += Hf[j * 4 + 2] * Hf[j * 4 + 2] + Hf[j * 4 + 3] * Hf[j * 4 + 3];
    }
    s0 += __shfl_xor_sync(0xFFFFFFFFu, s0, 1); s0 += __shfl_xor_sync(0xFFFFFFFFu, s0, 2);
    s1 += __shfl_xor_sync(0xFFFFFFFFu, s1, 1); s1 += __shfl_xor_sync(0xFFFFFFFFu, s1, 2);
    float n0 = sqrtf(s0), n1 = sqrtf(s1);
    float i0 = 1.0f / fmaxf(n0, 1e-12f), i1 = 1.0f / fmaxf(n1, 1e-12f);
    if ((lane & 3) == 0) {
        g_norm[(size_t)b * NN + nb0 + wid * 16 + (lane >> 2)] = n0;
        g_norm[(size_t)b * NN + nb0 + wid * 16 + (lane >> 2) + 8] = n1;
    }

    __syncthreads();  // done reading xs; reuse as hn staging
    {
        const int r = wid * 16 + (lane >> 2);
#pragma unroll
        for (int j = 0; j < 16; j++) {
            *(uint32_t*)(xs + r * 272 + j * 16 + 4 * (lane & 3)) =
                pack_h2(Hf[j * 4 + 0] * i0, Hf[j * 4 + 1] * i0);
            *(uint32_t*)(xs + (r + 8) * 272 + j * 16 + 4 * (lane & 3)) =
                pack_h2(Hf[j * 4 + 2] * i1, Hf[j * 4 + 3] * i1);
        }
    }
    __syncthreads();
    {
        unsigned short* hng = g_hn + ((size_t)b * NN + nb0) * CC;
#pragma unroll
        for (int it = 0; it < 8; it++) {
            int i = tid + it * 256;
            int row = i >> 4, ch = i & 15;
            *(float4*)(hng + (size_t)row * 128 + ch * 8) = *(const float4*)(xs + row * 272 + ch * 16);
        }
    }
}

// =====================================================================
// Kernel 2: S = hn_p.hn_q^T ; O += (edge*S*norm_q).hn_q ; ReLU
// grid (16,8), 256 threads: 8 warps, each m16 x FULL n128 (R8 structure).
// Edge read DIRECTLY from GMEM (no SMEM round-trip; zero reuse data),
// software-pipelined one tt ahead in registers.
// =====================================================================
#define OFF_T 0                          // 2 hn tiles (ping-pong)
#define OFF_N (2 * TILE_B)               // 2 x 128 norm floats
#define K2_SMEM (OFF_N + 1024)           // ~70.7 KB

// stage one 128x128 fp16 tile (row-major, 256B rows) -> SMEM pitch 272B (256 thr)
__device__ __forceinline__ void stage_tile(const unsigned short* src, char* dst, int tid) {
#pragma unroll
    for (int it = 0; it < 8; it++) {
        int i = tid + it * 256;
        int row = i >> 4, ch = i & 15;
        cp_async16(smem_u32(dst + row * 272 + ch * 16), src + (size_t)row * 128 + ch * 8);
    }
}

__global__ __launch_bounds__(256, 1) void k2_fused(const float* __restrict__ edge,
                                                   float* __restrict__ out) {
    extern __shared__ char smc[];
    const int b = blockIdx.y, p = blockIdx.x;
    const int tid = threadIdx.x, wid = tid >> 5, lane = tid & 31;

    const unsigned short* hnb = g_hn + (size_t)b * NN * CC;
    const float* eb = edge + ((size_t)b * NN + (size_t)p * 128) * NN;
    const float* nb = g_norm + (size_t)b * NN;

    // ---- preload A1 fragments (hn_p, m16 per warp, persistent) ----
    stage_tile(hnb + (size_t)p * 128 * CC, smc + OFF_T, tid);
    CP_COMMIT(); CP_WAIT0(); __syncthreads();

    uint32_t a1f[32];
    {
        uint32_t ra = smem_u32(smc + OFF_T) + (uint32_t)((wid * 16 + (lane & 15)) * 272)
                    + ((lane & 16) ? 16 : 0);
#pragma unroll
        for (int kk = 0; kk < 8; kk++) ldsm_x4(a1f + 4 * kk, ra + kk * 32);
    }
    __syncthreads();  // A1 in regs; tile buf 0 reusable

    float Of[64];
#pragma unroll
    for (int i = 0; i < 64; i++) Of[i] = 0.0f;

    // pipeline prologue: q=0 -> parity 0 buffers
    stage_tile(hnb, smc + OFF_T, tid);
    if (tid < 32) cp_async16(smem_u32(smc + OFF_N) + tid * 16, nb + tid * 4);
    CP_COMMIT();

    const int r0 = wid * 16 + (lane >> 2);   // m-row (within p-tile)
    const int c0 = 2 * (lane & 3);
    const uint32_t b1off = (uint32_t)(((lane & 7) + ((lane & 16) ? 8 : 0)) * 272)
                         + ((lane & 8) ? 16 : 0);

    // per-thread edge row pointers (rows r0, r0+8 of this p-tile)
    const float* er0p = eb + (size_t)r0 * NN;
    const float* er1p = eb + (size_t)(r0 + 8) * NN;

    // edge prefetch regs for current tt: [0]=(r0,cA) [1]=(r0+8,cA) [2]=(r0,cB) [3]=(r0+8,cB)
    float2 ec[4];
    ec[0] = ldg2(er0p + c0);
    ec[1] = ldg2(er1p + c0);
    ec[2] = ldg2(er0p + 8 + c0);
    ec[3] = ldg2(er1p + 8 + c0);

    for (int q = 0; q < NQT; q++) {
        const int par = q & 1;
        CP_WAIT0();
        __syncthreads();

        // prefetch q+1 tile/norms into opposite-parity buffers
        if (q < NQT - 1) {
            const int qn = q + 1, pn = par ^ 1;
            stage_tile(hnb + (size_t)qn * 128 * CC, smc + OFF_T + pn * TILE_B, tid);
            if (tid < 32)
                cp_async16(smem_u32(smc + OFF_N) + pn * 512 + tid * 16, nb + qn * 128 + tid * 4);
        }
        CP_COMMIT();

        const uint32_t b1base = smem_u32(smc + OFF_T + par * TILE_B) + b1off;
        const float* nbuf = (const float*)(smc + OFF_N + par * 512);
        const int qc = q * 128;

#pragma unroll
        for (int tt = 0; tt < 8; tt++) {
            // issue next-tt (or next-q tt0) edge loads early; latency hides under MMA1
            float2 en[4];
            {
                const int ncol = (tt < 7) ? (qc + (tt + 1) * 16) : ((q < NQT - 1) ? qc + 128 : qc);
                en[0] = ldg2(er0p + ncol + c0);
                en[1] = ldg2(er1p + ncol + c0);
                en[2] = ldg2(er0p + ncol + 8 + c0);
                en[3] = ldg2(er1p + ncol + 8 + c0);
            }

            // ---- MMA1: S[m16, n16] over k=128; keep B mats for MMA2 ----
            uint32_t bmat[8][4];
            float S[8];
#pragma unroll
            for (int i = 0; i < 8; i++) S[i] = 0.0f;
            {
                const uint32_t bb1 = b1base + (uint32_t)(tt * 16 * 272);
#pragma unroll
                for (int kk = 0; kk < 8; kk++) {
                    ldsm_x4(bmat[kk], bb1 + kk * 32);
                    mma16816(S + 0, a1f + 4 * kk, bmat[kk][0], bmat[kk][1]);
                    mma16816(S + 4, a1f + 4 * kk, bmat[kk][2], bmat[kk][3]);
                }
            }
            // ---- gate: S *= edge * norm_q ----
            {
                const int cA = tt * 16 + c0;
                const int cB = tt * 16 + 8 + c0;
                float2 nvA = *(const float2*)&nbuf[cA];
                float2 nvB = *(const float2*)&nbuf[cB];
                S[0] *= ec[0].x * nvA.x; S[1] *= ec[0].y * nvA.y;
                S[2] *= ec[1].x * nvA.x; S[3] *= ec[1].y * nvA.y;
                S[4] *= ec[2].x * nvB.x; S[5] *= ec[2].y * nvB.y;
                S[6] *= ec[3].x * nvB.x; S[7] *= ec[3].y * nvB.y;
            }
            // ---- pack A2 (m16 x k16) ----
            uint32_t A2[4];
            A2[0] = pack_h2(S[0], S[1]);
            A2[1] = pack_h2(S[2], S[3]);
            A2[2] = pack_h2(S[4], S[5]);
            A2[3] = pack_h2(S[6], S[7]);
            // ---- MMA2: O[m16, n128] += A2 . hn_q[k16, n128] ----
            // B fragments = movmatrix of MMA1's mats (no second ldsm)
#pragma unroll
            for (int j2 = 0; j2 < 16; j2++) {
                uint32_t b0 = movm(bmat[j2 >> 1][j2 & 1]);
                uint32_t b1 = movm(bmat[j2 >> 1][2 + (j2 & 1)]);
                mma16816(Of + j2 * 4, A2, b0, b1);
            }
            // rotate edge prefetch regs
            ec[0] = en[0]; ec[1] = en[1]; ec[2] = en[2]; ec[3] = en[3];
        }
    }

    // ---- epilogue: ReLU + store (no cross-warp reduction needed) ----
    {
        float* ob = out + ((size_t)b * NN + (size_t)p * 128) * CC;
#pragma unroll
        for (int j2 = 0; j2 < 16; j2++) {
            const int c = j2 * 8 + c0;
            float2 v0, v1;
            v0.x = fmaxf(Of[j2 * 4 + 0], 0.0f);
            v0.y = fmaxf(Of[j2 * 4 + 1], 0.0f);
            v1.x = fmaxf(Of[j2 * 4 + 2], 0.0f);
            v1.y = fmaxf(Of[j2 * 4 + 3], 0.0f);
            *(float2*)&ob[(size_t)r0 * CC + c] = v0;
            *(float2*)&ob[(size_t)(r0 + 8) * CC + c] = v1;
        }
    }
}

// ---------------- host launch ----------------
extern "C" void kernel_launch(void* const* d_in, const int* in_sizes, int n_in,
                              void* d_out, int out_size) {
    (void)out_size;
    const float *x = nullptr, *edge = nullptr, *W = nullptr, *bias = nullptr;
    for (int i = 0; i < n_in; i++) {
        int sz = in_sizes[i];
        if (sz == BB * NN * CC) x = (const float*)d_in[i];
        else if (sz == BB * NN * NN) edge = (const float*)d_in[i];
        else if (sz == CC * CC) W = (const float*)d_in[i];
        else if (sz == CC) bias = (const float*)d_in[i];
    }
    if (!x) x = (const float*)d_in[0];
    if (!edge) edge = (const float*)d_in[1];
    if (!W) W = (const float*)d_in[2];
    if (!bias) bias = (const float*)d_in[3];
    float* out = (float*)d_out;

    cudaFuncSetAttribute(k1_linear_norm, cudaFuncAttributeMaxDynamicSharedMemorySize, K1_SMEM);
    cudaFuncSetAttribute(k2_fused, cudaFuncAttributeMaxDynamicSharedMemorySize, K2_SMEM);

    k1_linear_norm<<<dim3(16, 8), 256, K1_SMEM>>>(x, W, bias);
    k2_fused<<<dim3(16, 8), 256, K2_SMEM>>>(edge, out);
}

// round 16
// speedup vs baseline: 1.1214x; 1.1214x over previous
#include <cuda_runtime.h>
#include <cuda_fp16.h>
#include <cstdint>

// Problem dims (fixed by dataset)
#define BB 8
#define NN 2048
#define CC 128
#define NQT 16  // NN / 128

// ---------------- scratch (device globals; no allocs allowed) ----------------
__device__ unsigned short g_hn[BB * NN * CC];  // normalized h, fp16, [b][n][c]
__device__ float g_norm[BB * NN];              // per-row L2 norm of h (fp32)

// ---------------- PTX helpers (family-portable: sm_75/80-era) ----------------
__device__ __forceinline__ uint32_t smem_u32(const void* p) {
    uint32_t a;
    asm("{ .reg .u64 t; cvta.to.shared.u64 t, %1; cvt.u32.u64 %0, t; }" : "=r"(a) : "l"(p));
    return a;
}

__device__ __forceinline__ void cp_async16(uint32_t dst, const void* src) {
    asm volatile("cp.async.cg.shared.global [%0], [%1], 16;" :: "r"(dst), "l"(src) : "memory");
}
#define CP_COMMIT() asm volatile("cp.async.commit_group;" ::: "memory")
#define CP_WAIT0()  asm volatile("cp.async.wait_group 0;" ::: "memory")

__device__ __forceinline__ void ldsm_x4(uint32_t* r, uint32_t a) {
    asm volatile("ldmatrix.sync.aligned.m8n8.x4.shared.b16 {%0,%1,%2,%3}, [%4];"
                 : "=r"(r[0]), "=r"(r[1]), "=r"(r[2]), "=r"(r[3]) : "r"(a));
}

// in-register 8x8 b16 transpose: converts MMA1 B-fragments into MMA2 B-fragments
__device__ __forceinline__ uint32_t movm(uint32_t a) {
    uint32_t d;
    asm volatile("movmatrix.sync.aligned.m8n8.trans.b16 %0, %1;" : "=r"(d) : "r"(a));
    return d;
}

__device__ __forceinline__ void mma16816(float* d, const uint32_t* a, uint32_t b0, uint32_t b1) {
    asm volatile("mma.sync.aligned.m16n8k16.row.col.f32.f16.f16.f32 "
                 "{%0,%1,%2,%3}, {%4,%5,%6,%7}, {%8,%9}, {%0,%1,%2,%3};"
                 : "+f"(d[0]), "+f"(d[1]), "+f"(d[2]), "+f"(d[3])
                 : "r"(a[0]), "r"(a[1]), "r"(a[2]), "r"(a[3]), "r"(b0), "r"(b1));
}

// pack two f32 -> f16x2 (lo = first arg)
__device__ __forceinline__ uint32_t pack_h2(float lo, float hi) {
    uint32_t d;
    asm("cvt.rn.f16x2.f32 %0, %1, %2;" : "=r"(d) : "f"(hi), "f"(lo));
    return d;
}

// =====================================================================
// Kernel 1: h = x@W^T + b (fp16 MMA) ; norm = ||h|| ; g_hn = h/norm (fp16)
// grid (16,8), 256 threads (8 warps x m16). SMEM: x-tile + W-tile fp16.
// =====================================================================
#define TILE_B 34816                     // 128 rows * 272B (fp16 tile, padded)
#define K1_SMEM (2 * TILE_B + 512)

__global__ __launch_bounds__(256) void k1_linear_norm(const float* __restrict__ x,
                                                      const float* __restrict__ W,
                                                      const float* __restrict__ bias) {
    extern __shared__ char sm1[];
    char* xs = sm1;                 // x tile fp16 (reused as hn stage later)
    char* Ws = sm1 + TILE_B;        // W tile fp16
    float* bs = (float*)(sm1 + 2 * TILE_B);

    const int b = blockIdx.y;
    const int nb0 = blockIdx.x * 128;
    const int tid = threadIdx.x, wid = tid >> 5, lane = tid & 31;

    // stage x and W (fp32 -> fp16), pitch 272B
    {
        const float* xg = x + ((size_t)b * NN + nb0) * CC;
#pragma unroll
        for (int it = 0; it < 16; it++) {
            int i = tid + it * 256;
            int row = i >> 5, c4 = i & 31;
            float4 v = *(const float4*)(xg + (size_t)row * 128 + c4 * 4);
            *(uint2*)(xs + row * 272 + c4 * 8) = make_uint2(pack_h2(v.x, v.y), pack_h2(v.z, v.w));
            float4 w4 = *(const float4*)(W + (size_t)row * 128 + c4 * 4);
            *(uint2*)(Ws + row * 272 + c4 * 8) = make_uint2(pack_h2(w4.x, w4.y), pack_h2(w4.z, w4.w));
        }
        if (tid < 32) *(float4*)&bs[tid * 4] = *(const float4*)(bias + tid * 4);
    }
    __syncthreads();

    // A fragments: warp's m16 rows of x
    uint32_t af[32];
    {
        uint32_t xa = smem_u32(xs) + (uint32_t)((wid * 16 + (lane & 15)) * 272)
                    + ((lane & 16) ? 16 : 0);
#pragma unroll
        for (int kk = 0; kk < 8; kk++) ldsm_x4(af + 4 * kk, xa + kk * 32);
    }

    float Hf[64];
#pragma unroll
    for (int i = 0; i < 64; i++) Hf[i] = 0.0f;

    // B = W rows (o = n dim), non-trans x4 (n16 x k16 per load)
    {
        uint32_t wb = smem_u32(Ws) + (uint32_t)(((lane & 7) + ((lane & 16) ? 8 : 0)) * 272)
                    + ((lane & 8) ? 16 : 0);
#pragma unroll
        for (int jp = 0; jp < 8; jp++) {
#pragma unroll
            for (int kk = 0; kk < 8; kk++) {
                uint32_t bf[4];
                ldsm_x4(bf, wb + (uint32_t)(jp * 16 * 272) + kk * 32);
                mma16816(Hf + (jp * 2) * 4, af + 4 * kk, bf[0], bf[1]);
                mma16816(Hf + (jp * 2 + 1) * 4, af + 4 * kk, bf[2], bf[3]);
            }
        }
    }

    // bias + row sum-of-squares
    float s0 = 0.0f, s1 = 0.0f;
#pragma unroll
    for (int j = 0; j < 16; j++) {
        float2 bv = *(const float2*)&bs[j * 8 + 2 * (lane & 3)];
        Hf[j * 4 + 0] += bv.x; Hf[j * 4 + 1] += bv.y;
        Hf[j * 4 + 2] += bv.x; Hf[j * 4 + 3] += bv.y;
        s0 += Hf[j * 4 + 0] * Hf[j * 4 + 0] + Hf[j * 4 + 1] * Hf[j * 4 + 1];
        s1 += Hf[j * 4 + 2] * Hf[j * 4 + 2] + Hf[j * 4 + 3] * Hf[j * 4 + 3];
    }
    s0 += __shfl_xor_sync(0xFFFFFFFFu, s0, 1); s0 += __shfl_xor_sync(0xFFFFFFFFu, s0, 2);
    s1 += __shfl_xor_sync(0xFFFFFFFFu, s1, 1); s1 += __shfl_xor_sync(0xFFFFFFFFu, s1, 2);
    float n0 = sqrtf(s0), n1 = sqrtf(s1);
    float i0 = 1.0f / fmaxf(n0, 1e-12f), i1 = 1.0f / fmaxf(n1, 1e-12f);
    if ((lane & 3) == 0) {
        g_norm[(size_t)b * NN + nb0 + wid * 16 + (lane >> 2)] = n0;
        g_norm[(size_t)b * NN + nb0 + wid * 16 + (lane >> 2) + 8] = n1;
    }

    __syncthreads();  // done reading xs; reuse as hn staging
    {
        const int r = wid * 16 + (lane >> 2);
#pragma unroll
        for (int j = 0; j < 16; j++) {
            *(uint32_t*)(xs + r * 272 + j * 16 + 4 * (lane & 3)) =
                pack_h2(Hf[j * 4 + 0] * i0, Hf[j * 4 + 1] * i0);
            *(uint32_t*)(xs + (r + 8) * 272 + j * 16 + 4 * (lane & 3)) =
                pack_h2(Hf[j * 4 + 2] * i1, Hf[j * 4 + 3] * i1);
        }
    }
    __syncthreads();
    {
        unsigned short* hng = g_hn + ((size_t)b * NN + nb0) * CC;
#pragma unroll
        for (int it = 0; it < 8; it++) {
            int i = tid + it * 256;
            int row = i >> 4, ch = i & 15;
            *(float4*)(hng + (size_t)row * 128 + ch * 8) = *(const float4*)(xs + row * 272 + ch * 16);
        }
    }
}

// =====================================================================
// Kernel 2: S = hn_p.hn_q^T ; O += (edge*S*norm_q).hn_q ; ReLU
// grid (32,8) = 256 CTAs, TWO per SM (105.5 KB SMEM each -> both fit).
// Independent barrier domains: each SMSP interleaves warps of different
// CTAs; one CTA's MMA stream covers the other's staging/gate/sync gaps.
// 128 threads: 4 warps, each m16 x FULL n128, bmat + movm (R8 shape).
// Edge staged via cp.async in HALF-q chunks (64 rows x 64 cols), R5-style
// half-pipelined: half1 loads during tt0-3; q+1 loads during tt4-7.
// =====================================================================
#define EBUFH 17408                      // 64 rows * 272B (64 cols fp32 + pad)
#define OFF_T 0                          // 2 hn tiles (ping-pong)
#define OFF_E (2 * TILE_B)               // 2 edge half-buffers
#define OFF_N (OFF_E + 2 * EBUFH)        // 2 x 128 norm floats
#define K2_SMEM (OFF_N + 1024)           // 105472 B/CTA; x2 = 210944 <= 227KB

// stage one 128x128 fp16 tile (row-major, 256B rows) -> SMEM pitch 272B (128 thr)
__device__ __forceinline__ void stage_tile(const unsigned short* src, char* dst, int tid) {
#pragma unroll
    for (int it = 0; it < 16; it++) {
        int i = tid + it * 128;
        int row = i >> 4, ch = i & 15;
        cp_async16(smem_u32(dst + row * 272 + ch * 16), src + (size_t)row * 128 + ch * 8);
    }
}
// stage 64-row fp16 tile (A1) -> SMEM pitch 272B (128 thr)
__device__ __forceinline__ void stage_tile64(const unsigned short* src, char* dst, int tid) {
#pragma unroll
    for (int it = 0; it < 8; it++) {
        int i = tid + it * 128;
        int row = i >> 4, ch = i & 15;
        cp_async16(smem_u32(dst + row * 272 + ch * 16), src + (size_t)row * 128 + ch * 8);
    }
}
// stage 64 rows x 64 floats of edge (gmem row pitch NN) -> SMEM pitch 272B (128 thr)
__device__ __forceinline__ void stage_edge_h(const float* src, char* dst, int tid) {
#pragma unroll
    for (int it = 0; it < 8; it++) {
        int i = tid + it * 128;
        int row = i >> 4, ch = i & 15;
        cp_async16(smem_u32(dst + row * 272 + ch * 16), src + (size_t)row * NN + ch * 4);
    }
}

__global__ __launch_bounds__(128, 2) void k2_fused(const float* __restrict__ edge,
                                                   float* __restrict__ out) {
    extern __shared__ char smc[];
    const int b = blockIdx.y, p = blockIdx.x;          // p: 0..31, m64 tiles
    const int tid = threadIdx.x, wid = tid >> 5, lane = tid & 31;

    const unsigned short* hnb = g_hn + (size_t)b * NN * CC;
    const float* eb = edge + ((size_t)b * NN + (size_t)p * 64) * NN;
    const float* nb = g_norm + (size_t)b * NN;

    // ---- preload A1 fragments (hn_p 64 rows, m16 per warp, persistent) ----
    stage_tile64(hnb + (size_t)p * 64 * CC, smc + OFF_T, tid);
    CP_COMMIT(); CP_WAIT0(); __syncthreads();

    uint32_t a1f[32];
    {
        uint32_t ra = smem_u32(smc + OFF_T) + (uint32_t)((wid * 16 + (lane & 15)) * 272)
                    + ((lane & 16) ? 16 : 0);
#pragma unroll
        for (int kk = 0; kk < 8; kk++) ldsm_x4(a1f + 4 * kk, ra + kk * 32);
    }
    __syncthreads();  // A1 in regs; tile buf 0 reusable

    float Of[64];
#pragma unroll
    for (int i = 0; i < 64; i++) Of[i] = 0.0f;

    // pipeline prologue: q=0 -> tile buf0, edge half0 -> ebuf0, norms par0
    stage_tile(hnb, smc + OFF_T, tid);
    stage_edge_h(eb, smc + OFF_E, tid);
    if (tid < 32) cp_async16(smem_u32(smc + OFF_N) + tid * 16, nb + tid * 4);
    CP_COMMIT();

    const int r0 = wid * 16 + (lane >> 2);   // m-row (local, 0..63)
    const int c0 = 2 * (lane & 3);
    const uint32_t b1off = (uint32_t)(((lane & 7) + ((lane & 16) ? 8 : 0)) * 272)
                         + ((lane & 8) ? 16 : 0);

    for (int q = 0; q < NQT; q++) {
        const int par = q & 1;
        const int qc = q * 128;
        CP_WAIT0();
        __syncthreads();   // tile(q), edge half0(q), norms(q) ready

        // issue edge half1(q) -> ebuf1 (spans tt0-3 compute)
        stage_edge_h(eb + qc + 64, smc + OFF_E + EBUFH, tid);
        CP_COMMIT();

        const uint32_t b1base = smem_u32(smc + OFF_T + par * TILE_B) + b1off;
        const float* nbuf = (const float*)(smc + OFF_N + par * 512);

#pragma unroll
        for (int half = 0; half < 2; half++) {
            const float* ebuf = (const float*)(smc + OFF_E + half * EBUFH);
#pragma unroll
            for (int t4 = 0; t4 < 4; t4++) {
                const int tt = half * 4 + t4;
                // ---- MMA1: S[m16, n16] over k=128; keep B mats for MMA2 ----
                uint32_t bmat[8][4];
                float S[8];
#pragma unroll
                for (int i = 0; i < 8; i++) S[i] = 0.0f;
                {
                    const uint32_t bb1 = b1base + (uint32_t)(tt * 16 * 272);
#pragma unroll
                    for (int kk = 0; kk < 8; kk++) {
                        ldsm_x4(bmat[kk], bb1 + kk * 32);
                        mma16816(S + 0, a1f + 4 * kk, bmat[kk][0], bmat[kk][1]);
                        mma16816(S + 4, a1f + 4 * kk, bmat[kk][2], bmat[kk][3]);
                    }
                }
                // ---- gate: S *= edge * norm_q ----
                {
                    const int lcA = t4 * 16 + c0;        // col within half (0..63)
                    const int lcB = t4 * 16 + 8 + c0;
                    const int cA = tt * 16 + c0;         // col within q (norms)
                    const int cB = tt * 16 + 8 + c0;
                    float2 nvA = *(const float2*)&nbuf[cA];
                    float2 nvB = *(const float2*)&nbuf[cB];
                    float2 e0A = *(const float2*)&ebuf[r0 * 68 + lcA];
                    float2 e1A = *(const float2*)&ebuf[(r0 + 8) * 68 + lcA];
                    float2 e0B = *(const float2*)&ebuf[r0 * 68 + lcB];
                    float2 e1B = *(const float2*)&ebuf[(r0 + 8) * 68 + lcB];
                    S[0] *= e0A.x * nvA.x; S[1] *= e0A.y * nvA.y;
                    S[2] *= e1A.x * nvA.x; S[3] *= e1A.y * nvA.y;
                    S[4] *= e0B.x * nvB.x; S[5] *= e0B.y * nvB.y;
                    S[6] *= e1B.x * nvB.x; S[7] *= e1B.y * nvB.y;
                }
                // ---- pack A2 (m16 x k16) ----
                uint32_t A2[4];
                A2[0] = pack_h2(S[0], S[1]);
                A2[1] = pack_h2(S[2], S[3]);
                A2[2] = pack_h2(S[4], S[5]);
                A2[3] = pack_h2(S[6], S[7]);
                // ---- MMA2: O[m16, n128] += A2 . hn_q[k16, n128] ----
#pragma unroll
                for (int j2 = 0; j2 < 16; j2++) {
                    uint32_t b0 = movm(bmat[j2 >> 1][j2 & 1]);
                    uint32_t b1 = movm(bmat[j2 >> 1][2 + (j2 & 1)]);
                    mma16816(Of + j2 * 4, A2, b0, b1);
                }
            }

            if (half == 0) {
                // mid-q: wait edge half1; then prefetch q+1 (spans tt4-7 compute)
                CP_WAIT0();
                __syncthreads();
                if (q < NQT - 1) {
                    const int qn = q + 1, pn = par ^ 1;
                    stage_tile(hnb + (size_t)qn * 128 * CC, smc + OFF_T + pn * TILE_B, tid);
                    stage_edge_h(eb + qn * 128, smc + OFF_E, tid);
                    if (tid < 32)
                        cp_async16(smem_u32(smc + OFF_N) + pn * 512 + tid * 16,
                                   nb + qn * 128 + tid * 4);
                }
                CP_COMMIT();
            }
        }
    }

    // ---- epilogue: ReLU + store ----
    {
        float* ob = out + ((size_t)b * NN + (size_t)p * 64) * CC;
#pragma unroll
        for (int j2 = 0; j2 < 16; j2++) {
            const int c = j2 * 8 + c0;
            float2 v0, v1;
            v0.x = fmaxf(Of[j2 * 4 + 0], 0.0f);
            v0.y = fmaxf(Of[j2 * 4 + 1], 0.0f);
            v1.x = fmaxf(Of[j2 * 4 + 2], 0.0f);
            v1.y = fmaxf(Of[j2 * 4 + 3], 0.0f);
            *(float2*)&ob[(size_t)r0 * CC + c] = v0;
            *(float2*)&ob[(size_t)(r0 + 8) * CC + c] = v1;
        }
    }
}

// ---------------- host launch ----------------
extern "C" void kernel_launch(void* const* d_in, const int* in_sizes, int n_in,
                              void* d_out, int out_size) {
    (void)out_size;
    const float *x = nullptr, *edge = nullptr, *W = nullptr, *bias = nullptr;
    for (int i = 0; i < n_in; i++) {
        int sz = in_sizes[i];
        if (sz == BB * NN * CC) x = (const float*)d_in[i];
        else if (sz == BB * NN * NN) edge = (const float*)d_in[i];
        else if (sz == CC * CC) W = (const float*)d_in[i];
        else if (sz == CC) bias = (const float*)d_in[i];
    }
    if (!x) x = (const float*)d_in[0];
    if (!edge) edge = (const float*)d_in[1];
    if (!W) W = (const float*)d_in[2];
    if (!bias) bias = (const float*)d_in[3];
    float* out = (float*)d_out;

    cudaFuncSetAttribute(k1_linear_norm, cudaFuncAttributeMaxDynamicSharedMemorySize, K1_SMEM);
    cudaFuncSetAttribute(k2_fused, cudaFuncAttributeMaxDynamicSharedMemorySize, K2_SMEM);

    k1_linear_norm<<<dim3(16, 8), 256, K1_SMEM>>>(x, W, bias);
    k2_fused<<<dim3(32, 8), 128, K2_SMEM>>>(edge, out);
}

// round 17
// speedup vs baseline: 1.1766x; 1.0492x over previous
#include <cuda_runtime.h>
#include <cuda_fp16.h>
#include <cstdint>

// Problem dims (fixed by dataset)
#define BB 8
#define NN 2048
#define CC 128
#define NQT 16  // NN / 128

// ---------------- scratch (device globals; no allocs allowed) ----------------
__device__ unsigned short g_hn[BB * NN * CC];  // normalized h, fp16, [b][n][c]
__device__ float g_norm[BB * NN];              // per-row L2 norm of h (fp32)

// ---------------- PTX helpers (family-portable: sm_75/80-era) ----------------
__device__ __forceinline__ uint32_t smem_u32(const void* p) {
    uint32_t a;
    asm("{ .reg .u64 t; cvta.to.shared.u64 t, %1; cvt.u32.u64 %0, t; }" : "=r"(a) : "l"(p));
    return a;
}

__device__ __forceinline__ void cp_async16(uint32_t dst, const void* src) {
    asm volatile("cp.async.cg.shared.global [%0], [%1], 16;" :: "r"(dst), "l"(src) : "memory");
}
#define CP_COMMIT() asm volatile("cp.async.commit_group;" ::: "memory")
#define CP_WAIT0()  asm volatile("cp.async.wait_group 0;" ::: "memory")

__device__ __forceinline__ void ldsm_x4(uint32_t* r, uint32_t a) {
    asm volatile("ldmatrix.sync.aligned.m8n8.x4.shared.b16 {%0,%1,%2,%3}, [%4];"
                 : "=r"(r[0]), "=r"(r[1]), "=r"(r[2]), "=r"(r[3]) : "r"(a));
}
__device__ __forceinline__ void ldsm_x4t(uint32_t* r, uint32_t a) {
    asm volatile("ldmatrix.sync.aligned.m8n8.x4.trans.shared.b16 {%0,%1,%2,%3}, [%4];"
                 : "=r"(r[0]), "=r"(r[1]), "=r"(r[2]), "=r"(r[3]) : "r"(a));
}

__device__ __forceinline__ void mma16816(float* d, const uint32_t* a, uint32_t b0, uint32_t b1) {
    asm volatile("mma.sync.aligned.m16n8k16.row.col.f32.f16.f16.f32 "
                 "{%0,%1,%2,%3}, {%4,%5,%6,%7}, {%8,%9}, {%0,%1,%2,%3};"
                 : "+f"(d[0]), "+f"(d[1]), "+f"(d[2]), "+f"(d[3])
                 : "r"(a[0]), "r"(a[1]), "r"(a[2]), "r"(a[3]), "r"(b0), "r"(b1));
}

// pack two f32 -> f16x2 (lo = first arg)
__device__ __forceinline__ uint32_t pack_h2(float lo, float hi) {
    uint32_t d;
    asm("cvt.rn.f16x2.f32 %0, %1, %2;" : "=r"(d) : "f"(hi), "f"(lo));
    return d;
}

// =====================================================================
// Kernel 1: h = x@W^T + b (fp16 MMA) ; norm = ||h|| ; g_hn = h/norm (fp16)
// grid (16,8), 256 threads (8 warps x m16). SMEM: x-tile + W-tile fp16.
// =====================================================================
#define TILE_B 34816                     // 128 rows * 272B (fp16 tile, padded)
#define K1_SMEM (2 * TILE_B + 512)

__global__ __launch_bounds__(256) void k1_linear_norm(const float* __restrict__ x,
                                                      const float* __restrict__ W,
                                                      const float* __restrict__ bias) {
    extern __shared__ char sm1[];
    char* xs = sm1;                 // x tile fp16 (reused as hn stage later)
    char* Ws = sm1 + TILE_B;        // W tile fp16
    float* bs = (float*)(sm1 + 2 * TILE_B);

    const int b = blockIdx.y;
    const int nb0 = blockIdx.x * 128;
    const int tid = threadIdx.x, wid = tid >> 5, lane = tid & 31;

    // stage x and W (fp32 -> fp16), pitch 272B
    {
        const float* xg = x + ((size_t)b * NN + nb0) * CC;
#pragma unroll
        for (int it = 0; it < 16; it++) {
            int i = tid + it * 256;
            int row = i >> 5, c4 = i & 31;
            float4 v = *(const float4*)(xg + (size_t)row * 128 + c4 * 4);
            *(uint2*)(xs + row * 272 + c4 * 8) = make_uint2(pack_h2(v.x, v.y), pack_h2(v.z, v.w));
            float4 w4 = *(const float4*)(W + (size_t)row * 128 + c4 * 4);
            *(uint2*)(Ws + row * 272 + c4 * 8) = make_uint2(pack_h2(w4.x, w4.y), pack_h2(w4.z, w4.w));
        }
        if (tid < 32) *(float4*)&bs[tid * 4] = *(const float4*)(bias + tid * 4);
    }
    __syncthreads();

    // A fragments: warp's m16 rows of x
    uint32_t af[32];
    {
        uint32_t xa = smem_u32(xs) + (uint32_t)((wid * 16 + (lane & 15)) * 272)
                    + ((lane & 16) ? 16 : 0);
#pragma unroll
        for (int kk = 0; kk < 8; kk++) ldsm_x4(af + 4 * kk, xa + kk * 32);
    }

    float Hf[64];
#pragma unroll
    for (int i = 0; i < 64; i++) Hf[i] = 0.0f;

    // B = W rows (o = n dim), non-trans x4 (n16 x k16 per load)
    {
        uint32_t wb = smem_u32(Ws) + (uint32_t)(((lane & 7) + ((lane & 16) ? 8 : 0)) * 272)
                    + ((lane & 8) ? 16 : 0);
#pragma unroll
        for (int jp = 0; jp < 8; jp++) {
#pragma unroll
            for (int kk = 0; kk < 8; kk++) {
                uint32_t bf[4];
                ldsm_x4(bf, wb + (uint32_t)(jp * 16 * 272) + kk * 32);
                mma16816(Hf + (jp * 2) * 4, af + 4 * kk, bf[0], bf[1]);
                mma16816(Hf + (jp * 2 + 1) * 4, af + 4 * kk, bf[2], bf[3]);
            }
        }
    }

    // bias + row sum-of-squares
    float s0 = 0.0f, s1 = 0.0f;
#pragma unroll
    for (int j = 0; j < 16; j++) {
        float2 bv = *(const float2*)&bs[j * 8 + 2 * (lane & 3)];
        Hf[j * 4 + 0] += bv.x; Hf[j * 4 + 1] += bv.y;
        Hf[j * 4 + 2] += bv.x; Hf[j * 4 + 3] += bv.y;
        s0 += Hf[j * 4 + 0] * Hf[j * 4 + 0] + Hf[j * 4 + 1] * Hf[j * 4 + 1];
        s1 += Hf[j * 4 + 2] * Hf[j * 4 + 2] + Hf[j * 4 + 3] * Hf[j * 4 + 3];
    }
    s0 += __shfl_xor_sync(0xFFFFFFFFu, s0, 1); s0 += __shfl_xor_sync(0xFFFFFFFFu, s0, 2);
    s1 += __shfl_xor_sync(0xFFFFFFFFu, s1, 1); s1 += __shfl_xor_sync(0xFFFFFFFFu, s1, 2);
    float n0 = sqrtf(s0), n1 = sqrtf(s1);
    float i0 = 1.0f / fmaxf(n0, 1e-12f), i1 = 1.0f / fmaxf(n1, 1e-12f);
    if ((lane & 3) == 0) {
        g_norm[(size_t)b * NN + nb0 + wid * 16 + (lane >> 2)] = n0;
        g_norm[(size_t)b * NN + nb0 + wid * 16 + (lane >> 2) + 8] = n1;
    }

    __syncthreads();  // done reading xs; reuse as hn staging
    {
        const int r = wid * 16 + (lane >> 2);
#pragma unroll
        for (int j = 0; j < 16; j++) {
            *(uint32_t*)(xs + r * 272 + j * 16 + 4 * (lane & 3)) =
                pack_h2(Hf[j * 4 + 0] * i0, Hf[j * 4 + 1] * i0);
            *(uint32_t*)(xs + (r + 8) * 272 + j * 16 + 4 * (lane & 3)) =
                pack_h2(Hf[j * 4 + 2] * i1, Hf[j * 4 + 3] * i1);
        }
    }
    __syncthreads();
    {
        unsigned short* hng = g_hn + ((size_t)b * NN + nb0) * CC;
#pragma unroll
        for (int it = 0; it < 8; it++) {
            int i = tid + it * 256;
            int row = i >> 4, ch = i & 15;
            *(float4*)(hng + (size_t)row * 128 + ch * 8) = *(const float4*)(xs + row * 272 + ch * 16);
        }
    }
}

// =====================================================================
// Kernel 2: two-phase per q through a gated SMEM tile.
//   Phase A (MMA1): warp (mi,ni) computes S[m32, n16] for its 4 interleaved
//     n-tiles T=2t+ni, gates by edge*norm, stores gated fp16 to SMEM tile.
//   Phase B (MMA2): warp (mi,ci) runs a pure burst: Of[m32,c64] += gated
//     [m32, k128] . hn_q[k128, c64] — 128 independent mmas, full k per warp.
// grid (16,8), 256 threads (8 warps). 1 CTA/SM, SMEM 175KB.
// =====================================================================
#define OFF_T 0                          // 2 hn tiles (ping-pong)
#define OFF_G (2 * TILE_B)               // gated fp16 tile [m128, k128], pitch 272
#define OFF_E (OFF_G + TILE_B)           // 2 edge half-buffers (128r x 64c fp32)
#define EBUFH 34816
#define OFF_N (OFF_E + 2 * EBUFH)        // 2 x 128 norm floats (parity)
#define K2_SMEM (OFF_N + 1024)           // 175104 B

// stage one 128x128 fp16 tile -> SMEM pitch 272B (256 thr)
__device__ __forceinline__ void stage_tile(const unsigned short* src, char* dst, int tid) {
#pragma unroll
    for (int it = 0; it < 8; it++) {
        int i = tid + it * 256;
        int row = i >> 4, ch = i & 15;
        cp_async16(smem_u32(dst + row * 272 + ch * 16), src + (size_t)row * 128 + ch * 8);
    }
}
// stage 128 rows x 64 floats of edge (gmem row pitch NN) -> SMEM pitch 272B (256 thr)
__device__ __forceinline__ void stage_edge_h(const float* src, char* dst, int tid) {
#pragma unroll
    for (int it = 0; it < 8; it++) {
        int i = tid + it * 256;
        int row = i >> 4, ch = i & 15;
        cp_async16(smem_u32(dst + row * 272 + ch * 16), src + (size_t)row * NN + ch * 4);
    }
}

__global__ __launch_bounds__(256, 1) void k2_fused(const float* __restrict__ edge,
                                                   float* __restrict__ out) {
    extern __shared__ char smc[];
    const int b = blockIdx.y, p = blockIdx.x;
    const int tid = threadIdx.x, wid = tid >> 5, lane = tid & 31;
    const int mi = wid & 3, ni = wid >> 2;   // ni doubles as ci for phase B

    const unsigned short* hnb = g_hn + (size_t)b * NN * CC;
    const float* eb = edge + ((size_t)b * NN + (size_t)p * 128) * NN;
    const float* nb = g_norm + (size_t)b * NN;

    // ---- preload A1 fragments (hn_p, m32 per warp, persistent) ----
    stage_tile(hnb + (size_t)p * 128 * CC, smc + OFF_T, tid);
    CP_COMMIT(); CP_WAIT0(); __syncthreads();

    uint32_t a1f[64];
    {
        uint32_t base = smem_u32(smc + OFF_T);
#pragma unroll
        for (int mt = 0; mt < 2; mt++) {
            uint32_t ra = base + (uint32_t)((mi * 32 + mt * 16 + (lane & 15)) * 272)
                        + ((lane & 16) ? 16 : 0);
#pragma unroll
            for (int kk = 0; kk < 8; kk++) ldsm_x4(a1f + mt * 32 + 4 * kk, ra + kk * 32);
        }
    }
    __syncthreads();  // A1 in regs; tile buf 0 reusable

    float Of[64];
#pragma unroll
    for (int i = 0; i < 64; i++) Of[i] = 0.0f;

    // prologue: tile(0) -> buf0, edge half0(0), norms(0)
    stage_tile(hnb, smc + OFF_T, tid);
    stage_edge_h(eb, smc + OFF_E, tid);
    if (tid < 32) cp_async16(smem_u32(smc + OFF_N) + tid * 16, nb + tid * 4);
    CP_COMMIT();

    const int rq = lane >> 2;                // quad row
    const int c0 = 2 * (lane & 3);
    const uint32_t b1off = (uint32_t)(((lane & 7) + ((lane & 16) ? 8 : 0)) * 272)
                         + ((lane & 8) ? 16 : 0);
    const uint32_t gbase = smem_u32(smc + OFF_G);

    for (int q = 0; q < NQT; q++) {
        const int par = q & 1;
        CP_WAIT0();
        __syncthreads();   // tile(q), edge half0(q), norms(q) ready; gated(q-1) consumed

        // C1: edge half1(q)
        stage_edge_h(eb + (size_t)q * 128 + 64, smc + OFF_E + EBUFH, tid);
        CP_COMMIT();

        const uint32_t tb = smem_u32(smc + OFF_T + par * TILE_B);
        const float* nbuf = (const float*)(smc + OFF_N + par * 512);

        // ================= Phase A: MMA1 + gate + store gated =================
#pragma unroll
        for (int t = 0; t < 4; t++) {
            if (t == 2) {  // half1 needed from here on
                CP_WAIT0();
                __syncthreads();
            }
            const int T = 2 * t + ni;        // n16-tile index; t<2 -> cols<64
            const int col = T * 16;
            float S[16];
#pragma unroll
            for (int i = 0; i < 16; i++) S[i] = 0.0f;
            {
                const uint32_t bb1 = tb + b1off + (uint32_t)(col * 272);
#pragma unroll
                for (int kk = 0; kk < 8; kk++) {
                    uint32_t bf[4];
                    ldsm_x4(bf, bb1 + kk * 32);
                    mma16816(S + 0,  a1f + 4 * kk,      bf[0], bf[1]);
                    mma16816(S + 4,  a1f + 4 * kk,      bf[2], bf[3]);
                    mma16816(S + 8,  a1f + 32 + 4 * kk, bf[0], bf[1]);
                    mma16816(S + 12, a1f + 32 + 4 * kk, bf[2], bf[3]);
                }
            }
            // gate + store gated fp16 (row-major, pitch 272)
            const float* ebuf = (const float*)(smc + OFF_E + (col >> 6) * EBUFH);
            const int lc = col & 63;
#pragma unroll
            for (int mt = 0; mt < 2; mt++) {
                const int r = mi * 32 + mt * 16 + rq;
#pragma unroll
                for (int jj = 0; jj < 2; jj++) {
                    const int cc = jj * 8 + c0;
                    float2 nv = *(const float2*)&nbuf[col + cc];
                    float2 e0 = *(const float2*)&ebuf[r * 68 + lc + cc];
                    float2 e1 = *(const float2*)&ebuf[(r + 8) * 68 + lc + cc];
                    const int si = mt * 8 + jj * 4;
                    uint32_t v0 = pack_h2(S[si + 0] * e0.x * nv.x, S[si + 1] * e0.y * nv.y);
                    uint32_t v1 = pack_h2(S[si + 2] * e1.x * nv.x, S[si + 3] * e1.y * nv.y);
                    *(uint32_t*)(smc + OFF_G + r * 272 + (col + cc) * 2) = v0;
                    *(uint32_t*)(smc + OFF_G + (r + 8) * 272 + (col + cc) * 2) = v1;
                }
            }
        }
        __syncthreads();   // gated tile fully written

        // C2: prefetch q+1 (tile, edge half0, norms) — covered by phase B
        if (q < NQT - 1) {
            const int qn = q + 1;
            stage_tile(hnb + (size_t)qn * 128 * CC, smc + OFF_T + (qn & 1) * TILE_B, tid);
            stage_edge_h(eb + (size_t)qn * 128, smc + OFF_E, tid);
            if (tid < 32)
                cp_async16(smem_u32(smc + OFF_N) + (qn & 1) * 512 + tid * 16,
                           nb + qn * 128 + tid * 4);
        }
        CP_COMMIT();

        // ================= Phase B: MMA2 burst (full k128 per warp) ==========
        {
            const uint32_t ga0 = gbase + (uint32_t)((mi * 32 + (lane & 15)) * 272)
                               + ((lane & 16) ? 16 : 0);
            const uint32_t bb2 = tb + (uint32_t)((lane & 15) * 272)
                               + ((lane & 16) ? 16 : 0) + (uint32_t)(ni * 64 * 2);
#pragma unroll
            for (int kk = 0; kk < 8; kk++) {
                uint32_t a2f[8];
                ldsm_x4(a2f + 0, ga0 + kk * 32);
                ldsm_x4(a2f + 4, ga0 + 16 * 272 + kk * 32);
                const uint32_t bk = bb2 + (uint32_t)(kk * 16 * 272);
#pragma unroll
                for (int j2p = 0; j2p < 4; j2p++) {
                    uint32_t bf[4];
                    ldsm_x4t(bf, bk + j2p * 32);
                    mma16816(Of + (j2p * 2) * 4,          a2f + 0, bf[0], bf[1]);
                    mma16816(Of + (j2p * 2 + 1) * 4,      a2f + 0, bf[2], bf[3]);
                    mma16816(Of + 32 + (j2p * 2) * 4,     a2f + 4, bf[0], bf[1]);
                    mma16816(Of + 32 + (j2p * 2 + 1) * 4, a2f + 4, bf[2], bf[3]);
                }
            }
        }
    }

    // ---- epilogue: ReLU + store (warp owns m32 rows mi*32, c64 cols ni*64) ----
    {
        float* ob = out + ((size_t)b * NN + (size_t)p * 128) * CC;
#pragma unroll
        for (int mt = 0; mt < 2; mt++) {
            const int r = mi * 32 + mt * 16 + rq;
#pragma unroll
            for (int j2 = 0; j2 < 8; j2++) {
                const int c = ni * 64 + j2 * 8 + c0;
                const int oi = mt * 32 + j2 * 4;
                float2 v0, v1;
                v0.x = fmaxf(Of[oi + 0], 0.0f);
                v0.y = fmaxf(Of[oi + 1], 0.0f);
                v1.x = fmaxf(Of[oi + 2], 0.0f);
                v1.y = fmaxf(Of[oi + 3], 0.0f);
                *(float2*)&ob[(size_t)r * CC + c] = v0;
                *(float2*)&ob[(size_t)(r + 8) * CC + c] = v1;
            }
        }
    }
}

// ---------------- host launch ----------------
extern "C" void kernel_launch(void* const* d_in, const int* in_sizes, int n_in,
                              void* d_out, int out_size) {
    (void)out_size;
    const float *x = nullptr, *edge = nullptr, *W = nullptr, *bias = nullptr;
    for (int i = 0; i < n_in; i++) {
        int sz = in_sizes[i];
        if (sz == BB * NN * CC) x = (const float*)d_in[i];
        else if (sz == BB * NN * NN) edge = (const float*)d_in[i];
        else if (sz == CC * CC) W = (const float*)d_in[i];
        else if (sz == CC) bias = (const float*)d_in[i];
    }
    if (!x) x = (const float*)d_in[0];
    if (!edge) edge = (const float*)d_in[1];
    if (!W) W = (const float*)d_in[2];
    if (!bias) bias = (const float*)d_in[3];
    float* out = (float*)d_out;

    cudaFuncSetAttribute(k1_linear_norm, cudaFuncAttributeMaxDynamicSharedMemorySize, K1_SMEM);
    cudaFuncSetAttribute(k2_fused, cudaFuncAttributeMaxDynamicSharedMemorySize, K2_SMEM);

    k1_linear_norm<<<dim3(16, 8), 256, K1_SMEM>>>(x, W, bias);
    k2_fused<<<dim3(16, 8), 256, K2_SMEM>>>(edge, out);
}